// round 17
// baseline (speedup 1.0000x reference)
#include <cuda_runtime.h>
#include <cstdint>

// Sparse 3D conv via warp-level fp16 mma.sync (m16n8k16), single pass.
// R17: two k-offsets per loop body (K=64 worth of MMAs = 16 per body) with
// the n32 accumulator tile (acc = 16 regs) so the double row-buffer fits in
// the proven 80-reg budget. 2x per-warp latency cover + 2x gather MLP vs R12.
// Gather loads predicate-guarded (@q ld.global.nc.v4) -> masked rows issue
// no memory traffic. Warp pair (n-halves) shares rows; twin loads hit L1.

static constexpr int kMVox = 100000;
static constexpr int kNVox = 200000;
static constexpr int kKVol = 27;
static constexpr int kCIn  = 32;
static constexpr int kCOut = 64;
static constexpr int M_TILE = 64;      // 8 warps: 4 row-groups x 2 n-halves

// feats converted to f16, channel-contiguous: [n][c], 64B per row
__device__ __align__(16) unsigned short g_f16[(size_t)kNVox * kCIn];

// B fragments, fp16, fragment-order with K-permutation:
// [koff][nb][lane] -> uint4 {w0..w3}, word j = f16x2(W[8t+2j][n], W[8t+2j+1][n])
__device__ __align__(16) uint4 g_bfrag[kKVol * 8 * 32];

__device__ __forceinline__ unsigned f16x2(float x, float y) {
    unsigned r;
    asm("cvt.rn.f16x2.f32 %0, %1, %2;" : "=r"(r) : "f"(y), "f"(x));  // x -> low half
    return r;
}

__global__ void prep_feats_kernel(const float* __restrict__ feats) {
    size_t i = (size_t)blockIdx.x * blockDim.x + threadIdx.x;   // one uint4 out
    if (i >= (size_t)kNVox * kCIn / 8) return;
    const float4* src = (const float4*)feats + 2 * i;
    float4 v0 = src[0], v1 = src[1];
    uint4 o;
    o.x = f16x2(v0.x, v0.y);
    o.y = f16x2(v0.z, v0.w);
    o.z = f16x2(v1.x, v1.y);
    o.w = f16x2(v1.z, v1.w);
    ((uint4*)g_f16)[i] = o;
}

__global__ void prep_kernel(const float* __restrict__ kw) {
    int koff = blockIdx.x, tid = threadIdx.x;       // 27 x 256
    int nb = tid >> 5, lane = tid & 31;
    int g = lane >> 2, t = lane & 3;
    int n = nb * 8 + g;
    const float* W = kw + koff * kCIn * kCOut;      // W[i][n]
    uint4 v;
    v.x = f16x2(W[(8 * t + 0) * kCOut + n], W[(8 * t + 1) * kCOut + n]);
    v.y = f16x2(W[(8 * t + 2) * kCOut + n], W[(8 * t + 3) * kCOut + n]);
    v.z = f16x2(W[(8 * t + 4) * kCOut + n], W[(8 * t + 5) * kCOut + n]);
    v.w = f16x2(W[(8 * t + 6) * kCOut + n], W[(8 * t + 7) * kCOut + n]);
    g_bfrag[(koff * 8 + nb) * 32 + lane] = v;
}

__device__ __forceinline__ void mma16816(float* d,
                                         unsigned a0, unsigned a1,
                                         unsigned a2, unsigned a3,
                                         unsigned b0, unsigned b1) {
    asm volatile(
        "mma.sync.aligned.m16n8k16.row.col.f32.f16.f16.f32 "
        "{%0,%1,%2,%3}, {%4,%5,%6,%7}, {%8,%9}, {%0,%1,%2,%3};"
        : "+f"(d[0]), "+f"(d[1]), "+f"(d[2]), "+f"(d[3])
        : "r"(a0), "r"(a1), "r"(a2), "r"(a3), "r"(b0), "r"(b1));
}

__global__ __launch_bounds__(256, 3)
void conv_hmma_kernel(const int* __restrict__ in_idx,
                      const int* __restrict__ mask,
                      float*     __restrict__ out) {
    const int w = threadIdx.x >> 5, lane = threadIdx.x & 31;
    const int g = lane >> 2, t = lane & 3;
    const int rg = w >> 1;            // row-group 0..3
    const int nh = w & 1;             // n-half 0..1
    const int mbase = blockIdx.x * M_TILE + rg * 16;
    const int mA = mbase + g;         // fragment rows g
    const int mB = mbase + g + 8;     // fragment rows g+8
    const bool vA = mA < kMVox, vB = mB < kMVox;

    // masked idx pair for offset k (independent loads, select after)
    auto ldidx = [&](int k, int& o0, int& o1) {
        size_t off = (size_t)k * kMVox;
        int mk0 = vA ? mask[off + mA] : 0;
        int ix0 = vA ? in_idx[off + mA] : 0;
        int mk1 = vB ? mask[off + mB] : 0;
        int ix1 = vB ? in_idx[off + mB] : 0;
        o0 = mk0 ? ix0 : -1;
        o1 = mk1 ? ix1 : -1;
    };
    // predicate-guarded fragment load: masked rows issue NO memory traffic
    auto ldrow = [&](int iv) -> uint4 {
        uint4 r = make_uint4(0u, 0u, 0u, 0u);
        const uint4* p = (const uint4*)(g_f16 + (size_t)(iv < 0 ? 0 : iv) * kCIn) + t;
        asm volatile(
            "{ .reg .pred q; setp.ge.s32 q, %4, 0;\n\t"
            "@q ld.global.nc.v4.u32 {%0,%1,%2,%3}, [%5]; }"
            : "+r"(r.x), "+r"(r.y), "+r"(r.z), "+r"(r.w)
            : "r"(iv), "l"(p));
        return r;
    };

    float acc[4][4];
#pragma unroll
    for (int i = 0; i < 4; ++i)
#pragma unroll
        for (int j = 0; j < 4; ++j) acc[i][j] = 0.f;

    // --- prologue: rows for offsets 0,1; idx for 2..5 in flight ---
    int i0, i1;
    ldidx(0, i0, i1);
    uint4 u0A = ldrow(i0), u0B = ldrow(i1);    // even offset of body
    ldidx(1, i0, i1);
    uint4 u1A = ldrow(i0), u1B = ldrow(i1);    // odd offset of body
    int j0a, j0b, j1a, j1b;                     // idx for next body (ready)
    ldidx(2, j0a, j0b);
    ldidx(3, j1a, j1b);
    int k0a, k0b, k1a, k1b;                     // idx for body+2 (in flight)
    ldidx(4, k0a, k0b);
    ldidx(5, k1a, k1b);

#pragma unroll 1
    for (int e = 0; e < kKVol - 1; e += 2) {
        // snapshot current fragments (u* get reloaded below)
        unsigned c0 = u0A.x, c1 = u0B.x, c2 = u0A.y, c3 = u0B.y;   // e, ks0
        unsigned d0 = u0A.z, d1 = u0B.z, d2 = u0A.w, d3 = u0B.w;   // e, ks1
        unsigned e0 = u1A.x, e1 = u1B.x, e2 = u1A.y, e3 = u1B.y;   // e+1, ks0
        unsigned f0 = u1A.z, f1 = u1B.z, f2 = u1A.w, f3 = u1B.w;   // e+1, ks1

        // issue rows for e+2, e+3 (cover = both MMA blocks below)
        if (e + 2 < kKVol) { u0A = ldrow(j0a); u0B = ldrow(j0b); }
        if (e + 3 < kKVol) { u1A = ldrow(j1a); u1B = ldrow(j1b); }
        // rotate idx pipeline; issue idx for e+6, e+7
        j0a = k0a; j0b = k0b; j1a = k1a; j1b = k1b;
        if (e + 6 < kKVol) ldidx(e + 6, k0a, k0b);
        if (e + 7 < kKVol) ldidx(e + 7, k1a, k1b);

        // --- MMA: offset e then e+1, this warp's 4 n-blocks x 2 k-steps ---
        const uint4* bp = g_bfrag + ((size_t)e * 8 + nh * 4) * 32 + lane;
#pragma unroll
        for (int nb = 0; nb < 4; ++nb) {
            uint4 bw = bp[nb * 32];
            mma16816(acc[nb], c0, c1, c2, c3, bw.x, bw.y);
            mma16816(acc[nb], d0, d1, d2, d3, bw.z, bw.w);
        }
        const uint4* bq = bp + 8 * 32;
#pragma unroll
        for (int nb = 0; nb < 4; ++nb) {
            uint4 bw = bq[nb * 32];
            mma16816(acc[nb], e0, e1, e2, e3, bw.x, bw.y);
            mma16816(acc[nb], f0, f1, f2, f3, bw.z, bw.w);
        }
    }

    // --- tail: offset 26 (rows already in u0) ---
    {
        const uint4* bp = g_bfrag + ((size_t)(kKVol - 1) * 8 + nh * 4) * 32 + lane;
#pragma unroll
        for (int nb = 0; nb < 4; ++nb) {
            uint4 bw = bp[nb * 32];
            mma16816(acc[nb], u0A.x, u0B.x, u0A.y, u0B.y, bw.x, bw.y);
            mma16816(acc[nb], u0A.z, u0B.z, u0A.w, u0B.w, bw.z, bw.w);
        }
    }

    // store: d0,d1 -> row mA ; d2,d3 -> row mB ; n-half offset nh*32
#pragma unroll
    for (int nb = 0; nb < 4; ++nb) {
        int n = nh * 32 + nb * 8 + 2 * t;
        if (vA)
            *(float2*)(out + (size_t)mA * kCOut + n) = make_float2(acc[nb][0], acc[nb][1]);
        if (vB)
            *(float2*)(out + (size_t)mB * kCOut + n) = make_float2(acc[nb][2], acc[nb][3]);
    }
}

extern "C" void kernel_launch(void* const* d_in, const int* in_sizes, int n_in,
                              void* d_out, int out_size) {
    const float* feats  = (const float*)d_in[0];
    const float* kernel = (const float*)d_in[1];
    const int*   in_idx = (const int*)d_in[2];
    const int*   maskp  = (const int*)d_in[3];
    float*       out    = (float*)d_out;
    (void)in_sizes; (void)n_in; (void)out_size;

    prep_feats_kernel<<<(int)(((size_t)kNVox * kCIn / 8 + 255) / 256), 256>>>(feats);
    prep_kernel<<<kKVol, 256>>>(kernel);
    int grid = (kMVox + M_TILE - 1) / M_TILE;   // 1563
    conv_hmma_kernel<<<grid, 256>>>(in_idx, maskp, out);
}